// round 14
// baseline (speedup 1.0000x reference)
#include <cuda_runtime.h>
#include <cuda_bf16.h>
#include <cstdint>

// ---------------- problem constants ----------------
#define BB   256
#define DD   200
#define ODIM 100
#define NO   5000
#define NL   50000
#define FCL  78
#define KD   80
#define NT   391

#define IMGW   168
#define IMGW32 84
#define TILE_U32  10752
#define TILE_U128 2688

#define BFRAG_PER_TILE (10 * 16 * 32)

#define NK1 1563
#define NK2 316
#define NK3 1564

typedef unsigned long long u64;

// ---------------- device scratch ----------------
__device__ float g_s[BB * ODIM];
__device__ float g_c[BB];
__device__ uint4 g_Aimg[2 * TILE_U128];
__device__ u64   g_Bfrag[NT * BFRAG_PER_TILE];

// ---------------- packed f32x2 helpers ----------------
__device__ __forceinline__ u64 add2(u64 a, u64 b) {
    u64 d; asm("add.rn.f32x2 %0,%1,%2;" : "=l"(d) : "l"(a), "l"(b)); return d;
}
__device__ __forceinline__ float2 u2f(u64 a) {
    float2 f; f.x = __uint_as_float((unsigned)a); f.y = __uint_as_float((unsigned)(a >> 32)); return f;
}

// ---------------- bf16 split helpers ----------------
__device__ __forceinline__ unsigned short f2bf(float x) {
    __nv_bfloat16 h = __float2bfloat16_rn(x);
    return *reinterpret_cast<unsigned short*>(&h);
}
__device__ __forceinline__ float bf2f(unsigned short u) {
    __nv_bfloat16_raw r; r.x = u;
    __nv_bfloat16 h = r;
    return __bfloat162float(h);
}
__device__ __forceinline__ unsigned pack_hi(float a, float b) {
    return (unsigned)f2bf(a) | ((unsigned)f2bf(b) << 16);
}
__device__ __forceinline__ unsigned pack_lo(float a, float b) {
    unsigned short ha = f2bf(a), hb = f2bf(b);
    unsigned short la = f2bf(a - bf2f(ha)), lb = f2bf(b - bf2f(hb));
    return (unsigned)la | ((unsigned)lb << 16);
}

// ---------------- warp MMA + TMA helpers ----------------
__device__ __forceinline__ uint32_t smem_u32(const void* p) {
    uint32_t a;
    asm("{ .reg .u64 t; cvta.to.shared.u64 t, %1; cvt.u32.u64 %0, t; }" : "=r"(a) : "l"(p));
    return a;
}
__device__ __forceinline__ void ldsm4(uint32_t r[4], uint32_t addr) {
    asm volatile("ldmatrix.sync.aligned.m8n8.x4.shared.b16 {%0,%1,%2,%3}, [%4];"
        : "=r"(r[0]), "=r"(r[1]), "=r"(r[2]), "=r"(r[3]) : "r"(addr));
}
__device__ __forceinline__ void mma_bf16(float c[4], const uint32_t a[4],
                                         uint32_t b0, uint32_t b1) {
    asm volatile(
        "mma.sync.aligned.m16n8k16.row.col.f32.bf16.bf16.f32 "
        "{%0,%1,%2,%3},{%4,%5,%6,%7},{%8,%9},{%0,%1,%2,%3};"
        : "+f"(c[0]), "+f"(c[1]), "+f"(c[2]), "+f"(c[3])
        : "r"(a[0]), "r"(a[1]), "r"(a[2]), "r"(a[3]), "r"(b0), "r"(b1));
}

#define MB_INIT(mb, c) \
    asm volatile("mbarrier.init.shared.b64 [%0], %1;" :: "r"(mb), "r"(c) : "memory")
#define MB_EXPECT(mb, bytes) \
    asm volatile("mbarrier.arrive.expect_tx.shared.b64 _, [%0], %1;" :: "r"(mb), "r"(bytes) : "memory")
#define BULK_G2S(dst, src, bytes, mb) \
    asm volatile("cp.async.bulk.shared::cta.global.mbarrier::complete_tx::bytes [%0], [%1], %2, [%3];" \
        :: "r"(dst), "l"(src), "r"(bytes), "r"(mb) : "memory")
#define MB_WAIT_P0(mb) do {                                                     \
    uint32_t _m = (mb);                                                         \
    asm volatile(                                                               \
        "{\n\t.reg .pred P1;\n\t"                                               \
        "WL_%=:\n\t"                                                            \
        "mbarrier.try_wait.parity.acquire.cta.shared::cta.b64 P1, [%0], 0, 0x989680;\n\t" \
        "@P1 bra.uni WD_%=;\n\t"                                                \
        "bra.uni WL_%=;\n\t"                                                    \
        "WD_%=:\n\t}"                                                           \
        :: "r"(_m) : "memory");                                                 \
} while (0)

// ============================================================
// kNop: filler to place the k1-only kA at sequence index 3
// ============================================================
__global__ void kNop() {}

// ============================================================
// Kernel A: k0 per-batch work (blocks 0..255) +
//           k1 conv features -> B fragments
// k1only != 0: every block is a k1 block (profiling re-run;
// idempotent — rewrites identical fragment values).
// ============================================================
#define K1R 32
__global__ void __launch_bounds__(256)
kA(const int* __restrict__ rel_idx,
   const int* __restrict__ rel2_idx,
   const int* __restrict__ user_idx,
   const int* __restrict__ hour_idx,
   const int* __restrict__ day_idx,
   const int* __restrict__ type_idx,
   const float* __restrict__ entity,
   const float* __restrict__ ont,
   const float* __restrict__ relation,
   const float* __restrict__ proj_W,
   const float* __restrict__ proj_b,
   const float* __restrict__ pR_W,
   const float* __restrict__ pR_b,
   const float* __restrict__ fc2_W,
   const float* __restrict__ fc2_b,
   const float* __restrict__ fc_W,
   const float* __restrict__ fc_b,
   const int k1only)
{
    const int tid = threadIdx.x;

    if (k1only || blockIdx.x >= BB) {
        // ---------------- k1: conv features -> B fragments ----------------
        __shared__ __align__(16) float e_sm[K1R * DD];
        __shared__ float f_sm[K1R][80];
        __shared__ float k_sm[20];
        __shared__ __align__(8) u64 mbar;

        const int n0 = (k1only ? blockIdx.x : (blockIdx.x - BB)) * K1R;
        // last block reads rows 50000..50015 — safe (NE=100000)

        if (tid == 0) MB_INIT(smem_u32(&mbar), 1);
        if (tid < 20) k_sm[tid] = fc2_W[tid * 6 + 4] + fc2_b[tid];
        if (tid < 64) f_sm[tid >> 1][78 + (tid & 1)] = 0.f;
        __syncthreads();

        if (tid == 0) {
            MB_EXPECT(smem_u32(&mbar), K1R * DD * 4);
            BULK_G2S(smem_u32(e_sm), entity + (long)n0 * DD,
                     K1R * DD * 4, smem_u32(&mbar));
        }
        MB_WAIT_P0(smem_u32(&mbar));

        for (int idx = tid; idx < K1R * 39; idx += 256) {
            const int row = idx / 39;
            const int w   = idx % 39;
            const float* e = &e_sm[row * DD + w * 5];
            float a0 = 0.f, a1 = 0.f;
            #pragma unroll
            for (int j = 0; j < 10; j++) {
                const float ev = e[j];
                a0 = fmaf(ev, k_sm[j],      a0);
                a1 = fmaf(ev, k_sm[10 + j], a1);
            }
            f_sm[row][w]      = a0;
            f_sm[row][39 + w] = a1;
        }
        __syncthreads();

        const int tile = n0 >> 7;
        const int jgb  = (n0 & 127) >> 3;
        u64* dst = g_Bfrag + (long)tile * BFRAG_PER_TILE;

        #pragma unroll
        for (int t = 0; t < 5; t++) {
            const int i  = tid + t * 256;
            const int l  = i & 31;
            const int j  = (i >> 5) & 3;
            const int ks = i >> 7;
            const int n  = j * 8 + (l >> 2);
            const int kp = (ks < 5 ? ks : ks - 5) * 16 + (l & 3) * 2;
            unsigned lo32, hi32;
            if (ks < 5) {
                lo32 = pack_hi(f_sm[n][kp],     f_sm[n][kp + 1]);
                hi32 = pack_hi(f_sm[n][kp + 8], f_sm[n][kp + 9]);
            } else {
                lo32 = pack_lo(f_sm[n][kp],     f_sm[n][kp + 1]);
                hi32 = pack_lo(f_sm[n][kp + 8], f_sm[n][kp + 9]);
            }
            dst[((ks * 16) + (jgb + j)) * 32 + l] = (u64)lo32 | ((u64)hi32 << 32);
        }
        return;
    }

    // ---------------- k0: per-batch vectors (R12 form) ----------------
    const int b = blockIdx.x;

    __shared__ float sm_rel2[DD];
    __shared__ float sm_ts[ODIM];
    __shared__ float sm_in[4][DD];
    __shared__ float sm_k[4][20];
    __shared__ float sm_y[4][80];
    __shared__ float sm_p[DD];
    __shared__ float sm_q[KD];
    __shared__ float sm_red[8];

    const int i_rel  = rel_idx[b];
    const int i_r2   = rel2_idx[b];
    const int i_type = type_idx[b];

    if (tid < DD)   sm_rel2[tid] = relation[i_r2 * DD + tid];
    if (tid < ODIM) sm_ts[tid]   = ont[i_type * ODIM + tid];
    {
        int idx0 = user_idx[b], idx1 = day_idx[b], idx2 = hour_idx[b];
        for (int i = tid; i < 3 * DD; i += 256) {
            const int s = i / DD, c = i % DD;
            const int row = (s == 0) ? idx0 : (s == 1) ? idx1 : idx2;
            sm_in[s][c] = entity[(long)row * DD + c];
        }
    }
    if (tid < 80) {
        const int s = tid / 20, w = tid % 20;
        const int poss[4] = {1, 2, 3, 5};
        sm_k[s][w] = fc2_W[w * 6 + poss[s]] + fc2_b[w];
    }
    __syncthreads();

    if (tid < ODIM) {
        const float* w = pR_W + tid * DD;
        float a0 = 0.f, a1 = 0.f, a2 = 0.f, a3 = 0.f;
        #pragma unroll
        for (int d = 0; d < DD; d += 4) {
            a0 = fmaf(sm_rel2[d],     w[d],     a0);
            a1 = fmaf(sm_rel2[d + 1], w[d + 1], a1);
            a2 = fmaf(sm_rel2[d + 2], w[d + 2], a2);
            a3 = fmaf(sm_rel2[d + 3], w[d + 3], a3);
        }
        const float v = (a0 + a1) + (a2 + a3) + pR_b[tid];
        g_s[b * ODIM + tid] = sm_ts[tid] + fmaxf(v, 0.f);
    }
    if (tid < DD) {
        const float* w = proj_W + tid * ODIM;
        float a0 = 0.f, a1 = 0.f, a2 = 0.f, a3 = 0.f;
        #pragma unroll
        for (int i = 0; i < ODIM; i += 4) {
            a0 = fmaf(sm_ts[i],     w[i],     a0);
            a1 = fmaf(sm_ts[i + 1], w[i + 1], a1);
            a2 = fmaf(sm_ts[i + 2], w[i + 2], a2);
            a3 = fmaf(sm_ts[i + 3], w[i + 3], a3);
        }
        sm_in[3][tid] = fmaxf((a0 + a1) + (a2 + a3) + proj_b[tid], 0.f);
    }
    __syncthreads();

    for (int i = tid; i < 4 * 80; i += 256) {
        const int s = i / 80, f = i % 80;
        float acc = 0.f;
        if (f < FCL) {
            const int ch = f / 39, w = f % 39;
            #pragma unroll
            for (int j = 0; j < 10; j++)
                acc = fmaf(sm_in[s][w * 5 + j], sm_k[s][ch * 10 + j], acc);
        }
        sm_y[s][f] = acc;
    }
    __syncthreads();

    if (tid < DD) {
        const float* w = fc_W + tid * FCL;
        const float bia = fc_b[tid];
        float au = bia, ad = bia, ah = bia, at = bia;
        #pragma unroll
        for (int f = 0; f < FCL; f++) {
            const float wv = w[f];
            au = fmaf(sm_y[0][f], wv, au);
            ad = fmaf(sm_y[1][f], wv, ad);
            ah = fmaf(sm_y[2][f], wv, ah);
            at = fmaf(sm_y[3][f], wv, at);
        }
        const float rel = relation[i_rel * DD + tid];
        sm_p[tid] = rel * au * ad * ah * at;
    }
    __syncthreads();

    if (tid < FCL) {
        float a0 = 0.f, a1 = 0.f, a2 = 0.f, a3 = 0.f;
        #pragma unroll
        for (int d = 0; d < DD; d += 4) {
            a0 = fmaf(sm_p[d],     fc_W[(d)     * FCL + tid], a0);
            a1 = fmaf(sm_p[d + 1], fc_W[(d + 1) * FCL + tid], a1);
            a2 = fmaf(sm_p[d + 2], fc_W[(d + 2) * FCL + tid], a2);
            a3 = fmaf(sm_p[d + 3], fc_W[(d + 3) * FCL + tid], a3);
        }
        sm_q[tid] = (a0 + a1) + (a2 + a3);
    } else if (tid < KD) {
        sm_q[tid] = 0.f;
    }

    float pc = 0.f;
    for (int d = tid; d < DD; d += 256) pc += sm_p[d] * fc_b[d];
    #pragma unroll
    for (int o = 16; o; o >>= 1) pc += __shfl_down_sync(0xffffffffu, pc, o);
    if ((tid & 31) == 0) sm_red[tid >> 5] = pc;
    __syncthreads();
    if (tid == 0) {
        float t = 0.f;
        #pragma unroll
        for (int w = 0; w < 8; w++) t += sm_red[w];
        g_c[b] = t;
    }

    if (tid < IMGW32) {
        const int tile = b >> 7;
        const int row  = b & 127;
        unsigned v = 0u;
        if (tid < 40) {
            v = pack_hi(sm_q[2 * tid], sm_q[2 * tid + 1]);
        } else if (tid < 80) {
            const int kk = (tid - 40) * 2;
            v = pack_lo(sm_q[kk], sm_q[kk + 1]);
        }
        reinterpret_cast<unsigned*>(g_Aimg)[tile * TILE_U32 + row * IMGW32 + tid] = v;
    }
}

// ============================================================
// Kernel B: k2 (blocks 0..315) + k3 (blocks 316..)
// ============================================================
#define K2SD 102
#define A_SLICE_BYTES 21504
__global__ void __launch_bounds__(256, 3)
kB(const float* __restrict__ ont, float* __restrict__ out)
{
    extern __shared__ __align__(16) char smraw[];
    const int tid = threadIdx.x;

    if (blockIdx.x >= NK2) {
        const int id   = blockIdx.x - NK2;
        const int nx   = id >> 2;
        const int my   = id & 3;
        const int wid  = tid >> 5;
        const int lane = tid & 31;

        const uint32_t a_base = smem_u32(smraw);
        const uint32_t mbar_a = a_base + A_SLICE_BYTES;

        if (tid == 0) MB_INIT(mbar_a, 1);
        __syncthreads();
        if (tid == 0) {
            const uint4* srcA = g_Aimg + (my >> 1) * TILE_U128 + (my & 1) * 1344;
            MB_EXPECT(mbar_a, A_SLICE_BYTES);
            BULK_G2S(a_base, (const void*)srcA, A_SLICE_BYTES, mbar_a);
        }

        const int wm = (wid & 1) * 32;
        const int wn = (wid >> 1) * 32;

        uint32_t aAddr[2];
        {
            const int ar = wm + (lane & 7) + ((lane >> 3) & 1) * 8;
            const int ac = ((lane >> 4) & 1) * 8;
            aAddr[0] = a_base + (ar * IMGW + ac) * 2;
            aAddr[1] = a_base + ((ar + 16) * IMGW + ac) * 2;
        }

        const u64* bbase = g_Bfrag + (long)nx * BFRAG_PER_TILE + ((wn >> 3) * 32) + lane;

        float acc[2][4][4];
        #pragma unroll
        for (int i = 0; i < 2; i++)
            #pragma unroll
            for (int j = 0; j < 4; j++)
                #pragma unroll
                for (int e = 0; e < 4; e++) acc[i][j][e] = 0.f;

        MB_WAIT_P0(mbar_a);

        #pragma unroll
        for (int t = 0; t < 5; t++) {
            uint32_t aH0[4], aH1[4], aL0[4], aL1[4];
            ldsm4(aH0, aAddr[0] + t * 32);
            ldsm4(aH1, aAddr[1] + t * 32);
            ldsm4(aL0, aAddr[0] + (t + 5) * 32);
            ldsm4(aL1, aAddr[1] + (t + 5) * 32);

            u64 bh[4], bl[4];
            #pragma unroll
            for (int jj = 0; jj < 4; jj++) {
                bh[jj] = bbase[(t * 16 + jj) * 32];
                bl[jj] = bbase[((t + 5) * 16 + jj) * 32];
            }

            #pragma unroll
            for (int g = 0; g < 4; g++) {
                const unsigned bhl = (unsigned)bh[g], bhh = (unsigned)(bh[g] >> 32);
                mma_bf16(acc[0][g], aH0, bhl, bhh);
                mma_bf16(acc[1][g], aH1, bhl, bhh);
                mma_bf16(acc[0][g], aL0, bhl, bhh);
                mma_bf16(acc[1][g], aL1, bhl, bhh);
                const unsigned bll = (unsigned)bl[g], blh = (unsigned)(bl[g] >> 32);
                mma_bf16(acc[0][g], aH0, bll, blh);
                mma_bf16(acc[1][g], aH1, bll, blh);
            }
        }

        float* hyp = out + BB * NO;
        const int mrow = my * 64 + wm + (lane >> 2);
        const int ncol = nx * 128 + wn + (lane & 3) * 2;

        #pragma unroll
        for (int mf = 0; mf < 2; mf++) {
            const int b0 = mrow + mf * 16;
            const float cb0 = g_c[b0];
            const float cb1 = g_c[b0 + 8];
            float* r0 = hyp + (long)b0 * NL;
            float* r1 = hyp + (long)(b0 + 8) * NL;
            #pragma unroll
            for (int j = 0; j < 4; j++) {
                const int n = ncol + j * 8;
                if (n < NL) {
                    float2 v0; v0.x = acc[mf][j][0] + cb0; v0.y = acc[mf][j][1] + cb0;
                    float2 v1; v1.x = acc[mf][j][2] + cb1; v1.y = acc[mf][j][3] + cb1;
                    *reinterpret_cast<float2*>(r0 + n) = v0;
                    *reinterpret_cast<float2*>(r1 + n) = v1;
                }
            }
        }
        return;
    }

    // ------------- k2: ontScores -------------
    const int id2 = blockIdx.x;
    const int o0  = (id2 % 79) * 64;
    const int b0  = (id2 / 79) * 64;

    float (*o_sm)[K2SD] = reinterpret_cast<float(*)[K2SD]>(smraw);
    float (*s_sm)[K2SD] = reinterpret_cast<float(*)[K2SD]>(smraw + 64 * K2SD * 4);

    for (int i = tid; i < 64 * ODIM; i += 256) {
        const int r = i / ODIM, c = i % ODIM;
        const int o = o0 + r;
        o_sm[r][c] = (o < NO) ? -ont[o * ODIM + c] : 0.f;
    }
    for (int i = tid; i < 64 * ODIM; i += 256) {
        const int r = i / ODIM, c = i % ODIM;
        s_sm[r][c] = g_s[(b0 + r) * ODIM + c];
    }
    __syncthreads();

    const int tx = tid & 15;
    const int ty = tid >> 4;

    const u64 AMASK = 0x7FFFFFFF7FFFFFFFULL;
    u64 acc[4][4];
    #pragma unroll
    for (int i = 0; i < 4; i++)
        #pragma unroll
        for (int j = 0; j < 4; j++) acc[i][j] = 0ULL;

    #pragma unroll 2
    for (int d = 0; d < ODIM; d += 2) {
        u64 sv[4];
        #pragma unroll
        for (int i = 0; i < 4; i++)
            sv[i] = *reinterpret_cast<const u64*>(&s_sm[ty * 4 + i][d]);
        #pragma unroll
        for (int j = 0; j < 4; j++) {
            const u64 ov = *reinterpret_cast<const u64*>(&o_sm[tx + 16 * j][d]);
            #pragma unroll
            for (int i = 0; i < 4; i++)
                acc[i][j] = add2(acc[i][j], add2(sv[i], ov) & AMASK);
        }
    }

    #pragma unroll
    for (int i = 0; i < 4; i++) {
        const int b = b0 + ty * 4 + i;
        #pragma unroll
        for (int j = 0; j < 4; j++) {
            const int o = o0 + tx + 16 * j;
            if (o < NO) {
                const float2 f = u2f(acc[i][j]);
                out[b * NO + o] = f.x + f.y;
            }
        }
    }
}

// ============================================================
// launcher — [kA, kB, kNop, kA(k1only)]; index 3 is the ncu
// target per the empirical skip-5 rule; wall-clock delta vs R12
// independently yields dur(k1-only).
// ============================================================
extern "C" void kernel_launch(void* const* d_in, const int* in_sizes, int n_in,
                              void* d_out, int out_size)
{
    const int*   rel_idx   = (const int*)  d_in[0];
    const int*   rel2_idx  = (const int*)  d_in[1];
    const int*   user_idx  = (const int*)  d_in[2];
    const int*   hour_idx  = (const int*)  d_in[3];
    const int*   day_idx   = (const int*)  d_in[4];
    const int*   type_idx  = (const int*)  d_in[5];
    // d_in[6] = currentBatchSize (always 256)
    const float* entity    = (const float*)d_in[7];
    const float* ont       = (const float*)d_in[8];
    const float* relation  = (const float*)d_in[9];
    const float* proj_W    = (const float*)d_in[10];
    const float* proj_b    = (const float*)d_in[11];
    const float* pR_W      = (const float*)d_in[12];
    const float* pR_b      = (const float*)d_in[13];
    const float* fc2_W     = (const float*)d_in[14];
    const float* fc2_b     = (const float*)d_in[15];
    const float* fc_W      = (const float*)d_in[16];
    const float* fc_b      = (const float*)d_in[17];
    float* out = (float*)d_out;

    const int kB_smem = 2 * 64 * K2SD * 4;
    cudaFuncSetAttribute(kB, cudaFuncAttributeMaxDynamicSharedMemorySize, kB_smem);

    kA<<<BB + NK1, 256>>>(rel_idx, rel2_idx, user_idx, hour_idx, day_idx, type_idx,
                          entity, ont, relation, proj_W, proj_b, pR_W, pR_b,
                          fc2_W, fc2_b, fc_W, fc_b, 0);

    kB<<<NK2 + NK3, 256, kB_smem>>>(ont, out);

    kNop<<<1, 32>>>();

    // k1-only re-run (idempotent) — profiling target at index 3
    kA<<<NK1, 256>>>(rel_idx, rel2_idx, user_idx, hour_idx, day_idx, type_idx,
                     entity, ont, relation, proj_W, proj_b, pR_W, pR_b,
                     fc2_W, fc2_b, fc_W, fc_b, 1);
}

// round 15
// speedup vs baseline: 1.4217x; 1.4217x over previous
#include <cuda_runtime.h>
#include <cuda_bf16.h>
#include <cstdint>

// ---------------- problem constants ----------------
#define BB   256
#define DD   200
#define ODIM 100
#define NO   5000
#define NL   50000
#define NR   100
#define FCL  78
#define KD   80
#define NT   391

#define IMGW   168
#define IMGW32 84
#define TILE_U32  10752
#define TILE_U128 2688

#define BFRAG_PER_TILE (10 * 16 * 32)

#define NSUB 50           // subRelAll blocks (2 r2-rows each)
#define NK1  1563
#define NK2  316
#define NK3  1564

typedef unsigned long long u64;

// ---------------- device scratch ----------------
__device__ float g_subAll[NR * ODIM];            // relu(relation @ pR_W.T + b)
__device__ float g_c[BB];
__device__ uint4 g_Aimg[2 * TILE_U128];
__device__ u64   g_Bfrag[NT * BFRAG_PER_TILE];

// ---------------- packed f32x2 helpers ----------------
__device__ __forceinline__ u64 add2(u64 a, u64 b) {
    u64 d; asm("add.rn.f32x2 %0,%1,%2;" : "=l"(d) : "l"(a), "l"(b)); return d;
}
__device__ __forceinline__ float2 u2f(u64 a) {
    float2 f; f.x = __uint_as_float((unsigned)a); f.y = __uint_as_float((unsigned)(a >> 32)); return f;
}

// ---------------- bf16 split helpers ----------------
__device__ __forceinline__ unsigned short f2bf(float x) {
    __nv_bfloat16 h = __float2bfloat16_rn(x);
    return *reinterpret_cast<unsigned short*>(&h);
}
__device__ __forceinline__ float bf2f(unsigned short u) {
    __nv_bfloat16_raw r; r.x = u;
    __nv_bfloat16 h = r;
    return __bfloat162float(h);
}
__device__ __forceinline__ unsigned pack_hi(float a, float b) {
    return (unsigned)f2bf(a) | ((unsigned)f2bf(b) << 16);
}
__device__ __forceinline__ unsigned pack_lo(float a, float b) {
    unsigned short ha = f2bf(a), hb = f2bf(b);
    unsigned short la = f2bf(a - bf2f(ha)), lb = f2bf(b - bf2f(hb));
    return (unsigned)la | ((unsigned)lb << 16);
}

// ---------------- warp MMA + TMA helpers ----------------
__device__ __forceinline__ uint32_t smem_u32(const void* p) {
    uint32_t a;
    asm("{ .reg .u64 t; cvta.to.shared.u64 t, %1; cvt.u32.u64 %0, t; }" : "=r"(a) : "l"(p));
    return a;
}
__device__ __forceinline__ void ldsm4(uint32_t r[4], uint32_t addr) {
    asm volatile("ldmatrix.sync.aligned.m8n8.x4.shared.b16 {%0,%1,%2,%3}, [%4];"
        : "=r"(r[0]), "=r"(r[1]), "=r"(r[2]), "=r"(r[3]) : "r"(addr));
}
__device__ __forceinline__ void mma_bf16(float c[4], const uint32_t a[4],
                                         uint32_t b0, uint32_t b1) {
    asm volatile(
        "mma.sync.aligned.m16n8k16.row.col.f32.bf16.bf16.f32 "
        "{%0,%1,%2,%3},{%4,%5,%6,%7},{%8,%9},{%0,%1,%2,%3};"
        : "+f"(c[0]), "+f"(c[1]), "+f"(c[2]), "+f"(c[3])
        : "r"(a[0]), "r"(a[1]), "r"(a[2]), "r"(a[3]), "r"(b0), "r"(b1));
}

#define MB_INIT(mb, c) \
    asm volatile("mbarrier.init.shared.b64 [%0], %1;" :: "r"(mb), "r"(c) : "memory")
#define MB_EXPECT(mb, bytes) \
    asm volatile("mbarrier.arrive.expect_tx.shared.b64 _, [%0], %1;" :: "r"(mb), "r"(bytes) : "memory")
#define BULK_G2S(dst, src, bytes, mb) \
    asm volatile("cp.async.bulk.shared::cta.global.mbarrier::complete_tx::bytes [%0], [%1], %2, [%3];" \
        :: "r"(dst), "l"(src), "r"(bytes), "r"(mb) : "memory")
#define MB_WAIT_P0(mb) do {                                                     \
    uint32_t _m = (mb);                                                         \
    asm volatile(                                                               \
        "{\n\t.reg .pred P1;\n\t"                                               \
        "WL_%=:\n\t"                                                            \
        "mbarrier.try_wait.parity.acquire.cta.shared::cta.b64 P1, [%0], 0, 0x989680;\n\t" \
        "@P1 bra.uni WD_%=;\n\t"                                                \
        "bra.uni WL_%=;\n\t"                                                    \
        "WD_%=:\n\t}"                                                           \
        :: "r"(_m) : "memory");                                                 \
} while (0)

// ============================================================
// Kernel A. Block ranges:
//  [0, 256)       k0 per-batch (smem-tiled gemvs)
//  [256, 306)     subRelAll (2 relation rows each)
//  [306, 1869)    k1 conv features -> B fragments
// All branches use the SAME dynamic smem buffer (36.9 KB).
// ============================================================
#define K1R 32
#define KA_DYN 37000
__global__ void __launch_bounds__(256, 3)
kA(const int* __restrict__ rel_idx,
   const int* __restrict__ rel2_idx,
   const int* __restrict__ user_idx,
   const int* __restrict__ hour_idx,
   const int* __restrict__ day_idx,
   const int* __restrict__ type_idx,
   const float* __restrict__ entity,
   const float* __restrict__ ont,
   const float* __restrict__ relation,
   const float* __restrict__ proj_W,
   const float* __restrict__ proj_b,
   const float* __restrict__ pR_W,
   const float* __restrict__ pR_b,
   const float* __restrict__ fc2_W,
   const float* __restrict__ fc2_b,
   const float* __restrict__ fc_W,
   const float* __restrict__ fc_b)
{
    extern __shared__ __align__(16) char smraw[];
    float* dyn = reinterpret_cast<float*>(smraw);
    const int tid = threadIdx.x;

    if (blockIdx.x >= BB + NSUB) {
        // ---------------- k1: conv features -> B fragments ----------------
        float* e_sm = dyn;                    // 32*200 = 6400
        float (*f_sm)[80] = reinterpret_cast<float(*)[80]>(dyn + 6400); // 2560
        float* k_sm = dyn + 8960;             // 20
        uint32_t mbar = smem_u32(dyn + 8982); // 8B aligned (offset 35928)

        const int n0 = (blockIdx.x - BB - NSUB) * K1R;
        // last block reads rows 50000..50015 — safe (NE=100000)

        if (tid == 0) MB_INIT(mbar, 1);
        if (tid < 20) k_sm[tid] = fc2_W[tid * 6 + 4] + fc2_b[tid];
        if (tid < 64) f_sm[tid >> 1][78 + (tid & 1)] = 0.f;
        __syncthreads();

        if (tid == 0) {
            MB_EXPECT(mbar, K1R * DD * 4);
            BULK_G2S(smem_u32(e_sm), entity + (long)n0 * DD, K1R * DD * 4, mbar);
        }
        MB_WAIT_P0(mbar);

        for (int idx = tid; idx < K1R * 39; idx += 256) {
            const int row = idx / 39;
            const int w   = idx % 39;
            const float* e = &e_sm[row * DD + w * 5];
            float a0 = 0.f, a1 = 0.f;
            #pragma unroll
            for (int j = 0; j < 10; j++) {
                const float ev = e[j];
                a0 = fmaf(ev, k_sm[j],      a0);
                a1 = fmaf(ev, k_sm[10 + j], a1);
            }
            f_sm[row][w]      = a0;
            f_sm[row][39 + w] = a1;
        }
        __syncthreads();

        const int tile = n0 >> 7;
        const int jgb  = (n0 & 127) >> 3;
        u64* dst = g_Bfrag + (long)tile * BFRAG_PER_TILE;

        #pragma unroll
        for (int t = 0; t < 5; t++) {
            const int i  = tid + t * 256;
            const int l  = i & 31;
            const int j  = (i >> 5) & 3;
            const int ks = i >> 7;
            const int n  = j * 8 + (l >> 2);
            const int kp = (ks < 5 ? ks : ks - 5) * 16 + (l & 3) * 2;
            unsigned lo32, hi32;
            if (ks < 5) {
                lo32 = pack_hi(f_sm[n][kp],     f_sm[n][kp + 1]);
                hi32 = pack_hi(f_sm[n][kp + 8], f_sm[n][kp + 9]);
            } else {
                lo32 = pack_lo(f_sm[n][kp],     f_sm[n][kp + 1]);
                hi32 = pack_lo(f_sm[n][kp + 8], f_sm[n][kp + 9]);
            }
            dst[((ks * 16) + (jgb + j)) * 32 + l] = (u64)lo32 | ((u64)hi32 << 32);
        }
        return;
    }

    if (blockIdx.x >= BB) {
        // ---------------- subRelAll: rows {2s, 2s+1} ----------------
        const int sblk = blockIdx.x - BB;
        float* w_sm   = dyn;          // 100*51 = 5100
        float* rel_sm = dyn + 5104;   // 2*200 = 400

        for (int i = tid; i < 2 * DD; i += 256)
            rel_sm[i] = relation[(long)(sblk * 2) * DD + i];

        const int o  = tid % 100;
        const int rh = tid / 100;     // active: tid < 200
        float acc = 0.f;

        for (int kt = 0; kt < DD; kt += 50) {
            __syncthreads();
            for (int i = tid; i < 100 * 50; i += 256) {
                const int r = i / 50, c = i % 50;
                w_sm[r * 51 + c] = pR_W[r * DD + kt + c];
            }
            __syncthreads();
            if (tid < 200) {
                #pragma unroll
                for (int c = 0; c < 50; c++)
                    acc = fmaf(w_sm[o * 51 + c], rel_sm[rh * DD + kt + c], acc);
            }
        }
        if (tid < 200)
            g_subAll[(sblk * 2 + rh) * ODIM + o] = fmaxf(acc + pR_b[o], 0.f);
        return;
    }

    // ---------------- k0: per-batch, smem-tiled gemvs ----------------
    const int b = blockIdx.x;

    float* w_sm = dyn;                 // up to 200*27 = 5400
    float* v    = dyn + 5408;
    float* sm_ts = v;                  // 100
    float (*sm_in)[DD] = reinterpret_cast<float(*)[DD]>(v + 104);  // 4*200
    float (*sm_k)[20]  = reinterpret_cast<float(*)[20]>(v + 904);  // 80
    float (*sm_y)[80]  = reinterpret_cast<float(*)[80]>(v + 984);  // 320
    float* sm_p = v + 1304;            // 200
    float* sm_q = v + 1504;            // 80
    float* sm_red = v + 1584;          // 8

    const int i_rel  = rel_idx[b];
    const int i_type = type_idx[b];

    // stage A: independent loads
    if (tid < ODIM) sm_ts[tid] = ont[i_type * ODIM + tid];
    {
        int idx0 = user_idx[b], idx1 = day_idx[b], idx2 = hour_idx[b];
        for (int i = tid; i < 3 * DD; i += 256) {
            const int s = i / DD, c = i % DD;
            const int row = (s == 0) ? idx0 : (s == 1) ? idx1 : idx2;
            sm_in[s][c] = entity[(long)row * DD + c];
        }
    }
    if (tid < 80) {
        const int s = tid / 20, w = tid % 20;
        const int poss[4] = {1, 2, 3, 5};
        sm_k[s][w] = fc2_W[w * 6 + poss[s]] + fc2_b[w];
    }

    // stage tt: smem-tiled gemv, thread-per-output (o = tid < 200)
    float acc_tt = (tid < DD) ? proj_b[tid] : 0.f;
    for (int dt = 0; dt < ODIM; dt += 25) {
        __syncthreads();
        for (int i = tid; i < DD * 25; i += 256) {
            const int r = i / 25, c = i % 25;
            w_sm[r * 25 + c] = proj_W[r * ODIM + dt + c];
        }
        __syncthreads();
        if (tid < DD) {
            #pragma unroll
            for (int c = 0; c < 25; c++)
                acc_tt = fmaf(w_sm[tid * 25 + c], sm_ts[dt + c], acc_tt);
        }
    }
    if (tid < DD) sm_in[3][tid] = fmaxf(acc_tt, 0.f);
    __syncthreads();

    // stage conv: 4 x 78 outputs
    for (int i = tid; i < 4 * 80; i += 256) {
        const int s = i / 80, f = i % 80;
        float acc = 0.f;
        if (f < FCL) {
            const int ch = f / 39, w = f % 39;
            #pragma unroll
            for (int j = 0; j < 10; j++)
                acc = fmaf(sm_in[s][w * 5 + j], sm_k[s][ch * 10 + j], acc);
        }
        sm_y[s][f] = acc;
    }

    // stage fc: smem-tiled, 4 accumulators, thread-per-output
    float au = 0.f, ad = 0.f, ah = 0.f, at = 0.f;
    for (int ft = 0; ft < FCL; ft += 26) {
        __syncthreads();
        for (int i = tid; i < DD * 26; i += 256) {
            const int r = i / 26, c = i % 26;
            w_sm[r * 27 + c] = fc_W[r * FCL + ft + c];
        }
        __syncthreads();
        if (tid < DD) {
            #pragma unroll
            for (int c = 0; c < 26; c++) {
                const float wv = w_sm[tid * 27 + c];
                au = fmaf(sm_y[0][ft + c], wv, au);
                ad = fmaf(sm_y[1][ft + c], wv, ad);
                ah = fmaf(sm_y[2][ft + c], wv, ah);
                at = fmaf(sm_y[3][ft + c], wv, at);
            }
        }
    }
    if (tid < DD) {
        const float bia = fc_b[tid];
        const float rel = relation[i_rel * DD + tid];
        sm_p[tid] = rel * (au + bia) * (ad + bia) * (ah + bia) * (at + bia);
    }
    __syncthreads();

    // stage q: coalesced global fc_W reads (column access)
    if (tid < FCL) {
        float a0 = 0.f, a1 = 0.f, a2 = 0.f, a3 = 0.f;
        #pragma unroll
        for (int d = 0; d < DD; d += 4) {
            a0 = fmaf(sm_p[d],     fc_W[(d)     * FCL + tid], a0);
            a1 = fmaf(sm_p[d + 1], fc_W[(d + 1) * FCL + tid], a1);
            a2 = fmaf(sm_p[d + 2], fc_W[(d + 2) * FCL + tid], a2);
            a3 = fmaf(sm_p[d + 3], fc_W[(d + 3) * FCL + tid], a3);
        }
        sm_q[tid] = (a0 + a1) + (a2 + a3);
    } else if (tid < KD) {
        sm_q[tid] = 0.f;
    }

    // c = p . fc_b
    float pc = 0.f;
    for (int d = tid; d < DD; d += 256) pc += sm_p[d] * fc_b[d];
    #pragma unroll
    for (int o = 16; o; o >>= 1) pc += __shfl_down_sync(0xffffffffu, pc, o);
    if ((tid & 31) == 0) sm_red[tid >> 5] = pc;
    __syncthreads();
    if (tid == 0) {
        float t = 0.f;
        #pragma unroll
        for (int w = 0; w < 8; w++) t += sm_red[w];
        g_c[b] = t;
    }

    // A-image row
    if (tid < IMGW32) {
        const int tile = b >> 7;
        const int row  = b & 127;
        unsigned val = 0u;
        if (tid < 40) {
            val = pack_hi(sm_q[2 * tid], sm_q[2 * tid + 1]);
        } else if (tid < 80) {
            const int kk = (tid - 40) * 2;
            val = pack_lo(sm_q[kk], sm_q[kk + 1]);
        }
        reinterpret_cast<unsigned*>(g_Aimg)[tile * TILE_U32 + row * IMGW32 + tid] = val;
    }
}

// ============================================================
// Kernel B: k2 (blocks 0..315; s gathered from ont + subRelAll)
//           + k3 (blocks 316..)
// ============================================================
#define K2SD 102
#define A_SLICE_BYTES 21504
__global__ void __launch_bounds__(256, 3)
kB(const float* __restrict__ ont,
   const int* __restrict__ rel2_idx,
   const int* __restrict__ type_idx,
   float* __restrict__ out)
{
    extern __shared__ __align__(16) char smraw[];
    const int tid = threadIdx.x;

    if (blockIdx.x >= NK2) {
        const int id   = blockIdx.x - NK2;
        const int nx   = id >> 2;
        const int my   = id & 3;
        const int wid  = tid >> 5;
        const int lane = tid & 31;

        const uint32_t a_base = smem_u32(smraw);
        const uint32_t mbar_a = a_base + A_SLICE_BYTES;

        if (tid == 0) MB_INIT(mbar_a, 1);
        __syncthreads();
        if (tid == 0) {
            const uint4* srcA = g_Aimg + (my >> 1) * TILE_U128 + (my & 1) * 1344;
            MB_EXPECT(mbar_a, A_SLICE_BYTES);
            BULK_G2S(a_base, (const void*)srcA, A_SLICE_BYTES, mbar_a);
        }

        const int wm = (wid & 1) * 32;
        const int wn = (wid >> 1) * 32;

        uint32_t aAddr[2];
        {
            const int ar = wm + (lane & 7) + ((lane >> 3) & 1) * 8;
            const int ac = ((lane >> 4) & 1) * 8;
            aAddr[0] = a_base + (ar * IMGW + ac) * 2;
            aAddr[1] = a_base + ((ar + 16) * IMGW + ac) * 2;
        }

        const u64* bbase = g_Bfrag + (long)nx * BFRAG_PER_TILE + ((wn >> 3) * 32) + lane;

        float acc[2][4][4];
        #pragma unroll
        for (int i = 0; i < 2; i++)
            #pragma unroll
            for (int j = 0; j < 4; j++)
                #pragma unroll
                for (int e = 0; e < 4; e++) acc[i][j][e] = 0.f;

        MB_WAIT_P0(mbar_a);

        #pragma unroll
        for (int t = 0; t < 5; t++) {
            uint32_t aH0[4], aH1[4], aL0[4], aL1[4];
            ldsm4(aH0, aAddr[0] + t * 32);
            ldsm4(aH1, aAddr[1] + t * 32);
            ldsm4(aL0, aAddr[0] + (t + 5) * 32);
            ldsm4(aL1, aAddr[1] + (t + 5) * 32);

            u64 bh[4], bl[4];
            #pragma unroll
            for (int jj = 0; jj < 4; jj++) {
                bh[jj] = bbase[(t * 16 + jj) * 32];
                bl[jj] = bbase[((t + 5) * 16 + jj) * 32];
            }

            #pragma unroll
            for (int g = 0; g < 4; g++) {
                const unsigned bhl = (unsigned)bh[g], bhh = (unsigned)(bh[g] >> 32);
                mma_bf16(acc[0][g], aH0, bhl, bhh);
                mma_bf16(acc[1][g], aH1, bhl, bhh);
                mma_bf16(acc[0][g], aL0, bhl, bhh);
                mma_bf16(acc[1][g], aL1, bhl, bhh);
                const unsigned bll = (unsigned)bl[g], blh = (unsigned)(bl[g] >> 32);
                mma_bf16(acc[0][g], aH0, bll, blh);
                mma_bf16(acc[1][g], aH1, bll, blh);
            }
        }

        float* hyp = out + BB * NO;
        const int mrow = my * 64 + wm + (lane >> 2);
        const int ncol = nx * 128 + wn + (lane & 3) * 2;

        #pragma unroll
        for (int mf = 0; mf < 2; mf++) {
            const int b0 = mrow + mf * 16;
            const float cb0 = g_c[b0];
            const float cb1 = g_c[b0 + 8];
            float* r0 = hyp + (long)b0 * NL;
            float* r1 = hyp + (long)(b0 + 8) * NL;
            #pragma unroll
            for (int j = 0; j < 4; j++) {
                const int n = ncol + j * 8;
                if (n < NL) {
                    float2 v0; v0.x = acc[mf][j][0] + cb0; v0.y = acc[mf][j][1] + cb0;
                    float2 v1; v1.x = acc[mf][j][2] + cb1; v1.y = acc[mf][j][3] + cb1;
                    *reinterpret_cast<float2*>(r0 + n) = v0;
                    *reinterpret_cast<float2*>(r1 + n) = v1;
                }
            }
        }
        return;
    }

    // ------------- k2: ontScores, s gathered on the fly -------------
    const int id2 = blockIdx.x;
    const int o0  = (id2 % 79) * 64;
    const int b0  = (id2 / 79) * 64;

    float (*o_sm)[K2SD] = reinterpret_cast<float(*)[K2SD]>(smraw);
    float (*s_sm)[K2SD] = reinterpret_cast<float(*)[K2SD]>(smraw + 64 * K2SD * 4);
    __shared__ int ids_t[64];
    __shared__ int ids_r[64];

    if (tid < 64)            ids_t[tid]      = type_idx[b0 + tid];
    else if (tid < 128)      ids_r[tid - 64] = rel2_idx[b0 + tid - 64];
    for (int i = tid; i < 64 * ODIM; i += 256) {
        const int r = i / ODIM, c = i % ODIM;
        const int o = o0 + r;
        o_sm[r][c] = (o < NO) ? -ont[o * ODIM + c] : 0.f;
    }
    __syncthreads();
    for (int i = tid; i < 64 * ODIM; i += 256) {
        const int r = i / ODIM, c = i % ODIM;
        s_sm[r][c] = ont[ids_t[r] * ODIM + c] + g_subAll[ids_r[r] * ODIM + c];
    }
    __syncthreads();

    const int tx = tid & 15;
    const int ty = tid >> 4;

    const u64 AMASK = 0x7FFFFFFF7FFFFFFFULL;
    u64 acc[4][4];
    #pragma unroll
    for (int i = 0; i < 4; i++)
        #pragma unroll
        for (int j = 0; j < 4; j++) acc[i][j] = 0ULL;

    #pragma unroll 2
    for (int d = 0; d < ODIM; d += 2) {
        u64 sv[4];
        #pragma unroll
        for (int i = 0; i < 4; i++)
            sv[i] = *reinterpret_cast<const u64*>(&s_sm[ty * 4 + i][d]);
        #pragma unroll
        for (int j = 0; j < 4; j++) {
            const u64 ov = *reinterpret_cast<const u64*>(&o_sm[tx + 16 * j][d]);
            #pragma unroll
            for (int i = 0; i < 4; i++)
                acc[i][j] = add2(acc[i][j], add2(sv[i], ov) & AMASK);
        }
    }

    #pragma unroll
    for (int i = 0; i < 4; i++) {
        const int b = b0 + ty * 4 + i;
        #pragma unroll
        for (int j = 0; j < 4; j++) {
            const int o = o0 + tx + 16 * j;
            if (o < NO) {
                const float2 f = u2f(acc[i][j]);
                out[b * NO + o] = f.x + f.y;
            }
        }
    }
}

// ============================================================
// launcher
// ============================================================
extern "C" void kernel_launch(void* const* d_in, const int* in_sizes, int n_in,
                              void* d_out, int out_size)
{
    const int*   rel_idx   = (const int*)  d_in[0];
    const int*   rel2_idx  = (const int*)  d_in[1];
    const int*   user_idx  = (const int*)  d_in[2];
    const int*   hour_idx  = (const int*)  d_in[3];
    const int*   day_idx   = (const int*)  d_in[4];
    const int*   type_idx  = (const int*)  d_in[5];
    // d_in[6] = currentBatchSize (always 256)
    const float* entity    = (const float*)d_in[7];
    const float* ont       = (const float*)d_in[8];
    const float* relation  = (const float*)d_in[9];
    const float* proj_W    = (const float*)d_in[10];
    const float* proj_b    = (const float*)d_in[11];
    const float* pR_W      = (const float*)d_in[12];
    const float* pR_b      = (const float*)d_in[13];
    const float* fc2_W     = (const float*)d_in[14];
    const float* fc2_b     = (const float*)d_in[15];
    const float* fc_W      = (const float*)d_in[16];
    const float* fc_b      = (const float*)d_in[17];
    float* out = (float*)d_out;

    const int kB_smem = 2 * 64 * K2SD * 4;
    cudaFuncSetAttribute(kA, cudaFuncAttributeMaxDynamicSharedMemorySize, KA_DYN);
    cudaFuncSetAttribute(kB, cudaFuncAttributeMaxDynamicSharedMemorySize, kB_smem);

    kA<<<BB + NSUB + NK1, 256, KA_DYN>>>(rel_idx, rel2_idx, user_idx, hour_idx,
                                         day_idx, type_idx, entity, ont, relation,
                                         proj_W, proj_b, pR_W, pR_b,
                                         fc2_W, fc2_b, fc_W, fc_b);

    kB<<<NK2 + NK3, 256, kB_smem>>>(ont, rel2_idx, type_idx, out);
}